// round 10
// baseline (speedup 1.0000x reference)
#include <cuda_runtime.h>

#define KNN_K 32
#define CUTOFF_SQ 100.0f
#define CUTOFF_SQ_BITS 0x42C80000u   // __float_as_uint(100.0f)

typedef unsigned long long u64;
#define SENTINEL 0xFFFFFFFFFFFFFFFFull

// Conditional-take compare-exchange. Equal keys are identical entries
// (key embeds the index), so either choice is correct on ties.
__device__ __forceinline__ void ce_swap(u64& key, u64 other, bool keep_min) {
    bool take = (other < key) == keep_min;
    if (take) key = other;
}

// Key for gathered candidate j (j >= ms by construction):
// (float_bits(masked_sq) << 32) | j. sq >= 0 so float bits are u32-monotone;
// u64 compare == (sq asc, idx asc) == reference (d asc, idx asc) since sqrt
// is monotone and sqrt_rn(100)=10 exactly. Out-of-range slots (j >= me) get
// SENTINEL: those row entries are fills already covered by the seed set, and
// sentinels can never be selected (32 seeds always rank below them).
__device__ __forceinline__ u64 gkey(int j, int i, int me,
                                    float xi, float yi, float zi, float sqni,
                                    const float* __restrict__ pos)
{
    if (j >= me) return SENTINEL;
    float xj = __ldg(pos + 3 * j);
    float yj = __ldg(pos + 3 * j + 1);
    float zj = __ldg(pos + 3 * j + 2);
    // Reference's gram-matrix expansion (numerical parity):
    float sqnj = xj * xj + yj * yj + zj * zj;
    float dt   = xi * xj + yi * yj + zi * zj;
    float sq   = sqni + sqnj - 2.0f * dt;
    sq = fmaxf(sq, 0.0f);
    bool masked = (j == i) | (sq > CUTOFF_SQ);
    float v = masked ? CUTOFF_SQ : sq;
    return ((u64)__float_as_uint(v) << 32) | (unsigned)j;
}

// Fallback: warp binary search (even lanes lower_bound, odd lanes upper_bound).
__device__ __forceinline__ void mol_bounds_bsearch(
    const int* __restrict__ batch, int n, int bi, int lane, int& ms, int& me)
{
    int lo = 0, hi = n;
    bool upper = (lane & 1);
    while (lo < hi) {
        int mid = (lo + hi) >> 1;
        int v = __ldg(batch + mid);
        bool go = upper ? (v <= bi) : (v < bi);
        if (go) lo = mid + 1; else hi = mid;
    }
    ms = __shfl_sync(0xffffffffu, lo, 0);
    me = __shfl_sync(0xffffffffu, lo, 1);
}

// One warp per row i.
// Exactness: the true top-32 of row i is drawn from
//   {candidates j in [ms, me)} ∪ {fills (100.0, j) for j outside [ms, me)}.
// The 32 smallest fills are exactly s_l = (l < ms) ? l : me + (l - ms)
// (any other fill has a larger index than all 32 of these and 32 entries
// rank at or below it, so it can never be in the top-32). We seed `held`
// with those and merge in every in-range candidate — exact for any ms/me.
__global__ void __launch_bounds__(128)
knn_kernel(const float* __restrict__ pos, const int* __restrict__ batch,
           float* __restrict__ out, int n)
{
    int w    = (blockIdx.x * blockDim.x + threadIdx.x) >> 5;
    int lane = threadIdx.x & 31;
    if (w >= n) return;
    // Load-balancing remap: molecules have different sizes (2-4 groups of
    // work); scatter rows so each SM gets a uniform mix. Bijective when n is
    // a power of two (odd multiplier); identity otherwise.
    int i = ((n & (n - 1)) == 0) ? ((w * 2731) & (n - 1)) : w;

    float xi = __ldg(pos + 3 * i);
    float yi = __ldg(pos + 3 * i + 1);
    float zi = __ldg(pos + 3 * i + 2);
    int   bi = __ldg(batch + i);
    float sqni = xi * xi + yi * yi + zi * zi;

    // ---- molecule bounds: 2-probe warp-cooperative search around i ----
    int ms, me;
    {
        // Phase A: stride-16 probes covering [i-256, i+240].
        int p = i + (lane - 16) * 16;
        bool inb = (p >= 0) && (p < n);
        bool eq  = inb && (__ldg(batch + p) == bi);
        unsigned m = __ballot_sync(0xffffffffu, eq);
        unsigned low_ne = (~m) & 0xFFFFu;
        unsigned hi_ne  = (~m) >> 16;

        if (low_ne == 0u || hi_ne == 0u) {
            mol_bounds_bsearch(batch, n, bi, lane, ms, me);  // exact fallback
        } else {
            int l_lo = 31 - __clz(low_ne);
            int l_hi = 16 + (__ffs(hi_ne) - 1);
            int lo_base = i + (l_lo - 16) * 16 + 1;
            int hi_end  = i + (l_hi - 16) * 16;
            int q;
            bool eq2;
            if (lane < 16) {
                q = lo_base + lane;
                eq2 = (q >= 0) && (__ldg(batch + q) == bi);
            } else {
                q = hi_end - 31 + lane;
                eq2 = (q < n) && (__ldg(batch + q) == bi);
            }
            unsigned m2 = __ballot_sync(0xffffffffu, eq2);
            unsigned lom = m2 & 0xFFFFu;
            unsigned him = m2 >> 16;
            ms = lo_base + (__ffs(lom) - 1);
            me = hi_end - 15 + (32 - __clz(him));
        }
    }

    // ---- seed held with the 32 smallest fill entries (sorted asc) ----
    int sidx = (lane < ms) ? lane : me + (lane - ms);
    u64 held = (sidx < n) ? (((u64)CUTOFF_SQ_BITS << 32) | (unsigned)sidx)
                          : SENTINEL;

    int T = ((me - ms) + 31) >> 5;   // number of 32-candidate groups
    int t = 0;

    // ---- paired groups: sort A asc & B desc interleaved (2-wide ILP) ----
    while (t + 1 < T) {
        u64 A = gkey(ms + t * 32 + lane,       i, me, xi, yi, zi, sqni, pos);
        u64 B = gkey(ms + (t + 1) * 32 + lane, i, me, xi, yi, zi, sqni, pos);
        #pragma unroll
        for (int k = 2; k <= 32; k <<= 1) {
            #pragma unroll
            for (int j = k >> 1; j >= 1; j >>= 1) {
                u64 oA = __shfl_xor_sync(0xffffffffu, A, j);
                u64 oB = __shfl_xor_sync(0xffffffffu, B, j);
                bool km = (((lane & k) == 0) == ((lane & j) == 0));
                ce_swap(A, oA, km);    // ascending
                ce_swap(B, oB, !km);   // descending
            }
        }
        // top-32 of A∪B: elementwise min of (asc, desc) is bitonic and holds
        // exactly the 32 smallest; 5-stage cleanup sorts it DESC.
        u64 ab = (A < B) ? A : B;
        #pragma unroll
        for (int j = 16; j >= 1; j >>= 1) {
            u64 o = __shfl_xor_sync(0xffffffffu, ab, j);
            ce_swap(ab, o, (lane & j) != 0);
        }
        // merge into held (asc): min(asc, desc) + 5-stage asc cleanup.
        u64 lo = (held < ab) ? held : ab;
        #pragma unroll
        for (int j = 16; j >= 1; j >>= 1) {
            u64 o = __shfl_xor_sync(0xffffffffu, lo, j);
            ce_swap(lo, o, (lane & j) == 0);
        }
        held = lo;
        t += 2;
    }

    // ---- tail group (if odd count): sort desc + merge ----
    if (t < T) {
        u64 A = gkey(ms + t * 32 + lane, i, me, xi, yi, zi, sqni, pos);
        #pragma unroll
        for (int k = 2; k <= 32; k <<= 1) {
            #pragma unroll
            for (int j = k >> 1; j >= 1; j >>= 1) {
                u64 oA = __shfl_xor_sync(0xffffffffu, A, j);
                bool km = (((lane & k) == 0) == ((lane & j) == 0));
                ce_swap(A, oA, !km);   // descending
            }
        }
        u64 lo = (held < A) ? held : A;
        #pragma unroll
        for (int j = 16; j >= 1; j >>= 1) {
            u64 o = __shfl_xor_sync(0xffffffffu, lo, j);
            ce_swap(lo, o, (lane & j) == 0);
        }
        held = lo;
    }

    // Output: [edge_index[0] (N*K), edge_index[1] (N*K), edge_weight (N*K)]
    unsigned int nb = (unsigned int)(held & 0xffffffffu);
    float sqv = __uint_as_float((unsigned int)(held >> 32));
    float wgt = sqrtf(sqv);               // sqrt(100)=10 exactly for fills/masked
    int NK = n * KNN_K;
    int base = i * KNN_K + lane;
    out[base]          = (float)nb;       // neighbor index
    out[NK + base]     = (float)i;        // source row
    out[2 * NK + base] = wgt;             // distance weight
}

extern "C" void kernel_launch(void* const* d_in, const int* in_sizes, int n_in,
                              void* d_out, int out_size)
{
    const float* pos   = (const float*)d_in[0];
    const int*   batch = (const int*)d_in[1];
    float*       out   = (float*)d_out;
    int n = in_sizes[1];  // batch has N elements

    int threads = 128;                       // 4 warps/block, 1 warp per row
    int blocks  = (n * 32 + threads - 1) / threads;
    knn_kernel<<<blocks, threads>>>(pos, batch, out, n);
}

// round 11
// speedup vs baseline: 1.1382x; 1.1382x over previous
#include <cuda_runtime.h>

#define KNN_K 32
#define CUTOFF_SQ 100.0f   // cutoff=10.0; sort in squared space, sqrt once at output

typedef unsigned long long u64;

// Conditional-take compare-exchange. Equal u64 keys are identical entries
// (key embeds the index), so either choice is correct on ties.
__device__ __forceinline__ void ce_swap(u64& key, u64 other, bool keep_min) {
    bool take = (other < key) == keep_min;
    if (take) key = other;
}

// Full 32-lane bitonic sort. ASC=true: lane l holds l-th smallest.
template <bool ASC>
__device__ __forceinline__ u64 bitonic_sort32(u64 key, int lane) {
    #pragma unroll
    for (int k = 2; k <= 32; k <<= 1) {
        #pragma unroll
        for (int j = k >> 1; j >= 1; j >>= 1) {
            u64 other = __shfl_xor_sync(0xffffffffu, key, j);
            bool keep_min = (((lane & k) == 0) == ((lane & j) == 0));
            if (!ASC) keep_min = !keep_min;
            ce_swap(key, other, keep_min);
        }
    }
    return key;
}

// held sorted asc, cand sorted DESC: elementwise min is a bitonic sequence
// containing exactly the 32 smallest of the 64; 5-stage merge re-sorts asc.
__device__ __forceinline__ u64 merge_keep32(u64 held, u64 cand_desc, int lane) {
    u64 lo = (held < cand_desc) ? held : cand_desc;
    #pragma unroll
    for (int j = 16; j >= 1; j >>= 1) {
        u64 other = __shfl_xor_sync(0xffffffffu, lo, j);
        ce_swap(lo, other, (lane & j) == 0);
    }
    return lo;
}

// Key for candidate j = c*32+lane: (float_bits(masked_sq) << 32) | j.
// sq >= 0 so float bits are u32-monotone; u64 compare == (sq asc, idx asc)
// == reference (d asc, idx asc) since sqrt is monotone and sqrt_rn(100)=10
// exactly. Cross-batch mask via [ms, me) range (batch sorted) — no batch load.
__device__ __forceinline__ u64 chunk_key(
    int c, int lane, int n, int i, int ms, int me,
    float xi, float yi, float zi, float sqni, const float* __restrict__ pos)
{
    int j = (c << 5) + lane;
    if (j >= n) return 0xFFFFFFFFFFFFFFFFull;
    float xj = __ldg(pos + 3 * j);
    float yj = __ldg(pos + 3 * j + 1);
    float zj = __ldg(pos + 3 * j + 2);
    // Reference's gram-matrix expansion (numerical parity):
    float sqnj = xj * xj + yj * yj + zj * zj;
    float dt   = xi * xj + yi * yj + zi * zj;
    float sq   = sqni + sqnj - 2.0f * dt;
    sq = fmaxf(sq, 0.0f);
    bool masked = (j == i) | (j < ms) | (j >= me) | (sq > CUTOFF_SQ);
    float v = masked ? CUTOFF_SQ : sq;
    return ((u64)__float_as_uint(v) << 32) | (unsigned)j;
}

// Fallback: warp binary search (even lanes lower_bound, odd lanes upper_bound).
__device__ __forceinline__ void mol_bounds_bsearch(
    const int* __restrict__ batch, int n, int bi, int lane, int& ms, int& me)
{
    int lo = 0, hi = n;
    bool upper = (lane & 1);
    while (lo < hi) {
        int mid = (lo + hi) >> 1;
        int v = __ldg(batch + mid);
        bool go = upper ? (v <= bi) : (v < bi);
        if (go) lo = mid + 1; else hi = mid;
    }
    ms = __shfl_sync(0xffffffffu, lo, 0);
    me = __shfl_sync(0xffffffffu, lo, 1);
}

// One warp per row i. Pruning exactness: if ms>=32, candidates j=0..31 are all
// cross-batch masked, so the true entries there are exactly (100.0, 0..31) —
// seed held with that constant. Held max <= (100.0, 31), so any masked key
// (100.0, j>=32) can never enter the top-32; only chunks overlapping [ms,me)
// need processing. If ms<32, process chunk 0 with real masks first.
__global__ void __launch_bounds__(256)
knn_kernel(const float* __restrict__ pos, const int* __restrict__ batch,
           float* __restrict__ out, int n)
{
    int w    = (blockIdx.x * blockDim.x + threadIdx.x) >> 5;
    int lane = threadIdx.x & 31;
    if (w >= n) return;

    // Stratified row mapping: block b's 8 warps take rows b, b+n/8, ..., b+7n/8.
    // Per-block work becomes an 8-stratum sample instead of one molecule's
    // (2-4x variable) cost, equalizing per-SM instruction mass in the single
    // resident wave. Bijective when 8 | n; identity fallback otherwise.
    int i;
    if ((n & 7) == 0) {
        int stratum = w & 7;           // warp slot within block (warps are
        int off     = w >> 3;          // block-major: w = b*8 + k)
        i = stratum * (n >> 3) + off;
    } else {
        i = w;
    }

    float xi = __ldg(pos + 3 * i);
    float yi = __ldg(pos + 3 * i + 1);
    float zi = __ldg(pos + 3 * i + 2);
    int   bi = __ldg(batch + i);
    float sqni = xi * xi + yi * yi + zi * zi;

    // ---- molecule bounds: 2-probe warp-cooperative search around i ----
    // batch is sorted and batch[i]==bi, so the molecule's range surrounds i.
    int ms, me;
    {
        // Phase A: stride-16 probes covering [i-256, i+240].
        int p = i + (lane - 16) * 16;
        bool inb = (p >= 0) && (p < n);
        bool eq  = inb && (__ldg(batch + p) == bi);
        unsigned m = __ballot_sync(0xffffffffu, eq);
        unsigned low_ne = (~m) & 0xFFFFu;   // lanes 0..15 not-equal
        unsigned hi_ne  = (~m) >> 16;       // lanes 16..31 not-equal (lane16 = i)

        if (low_ne == 0u || hi_ne == 0u) {
            // molecule extends beyond the +-256 window — exact fallback
            mol_bounds_bsearch(batch, n, bi, lane, ms, me);
        } else {
            int l_lo = 31 - __clz(low_ne);          // largest ne lane below 16
            int l_hi = 16 + (__ffs(hi_ne) - 1);     // smallest ne lane above 16
            int lo_base = i + (l_lo - 16) * 16 + 1; // ms in [lo_base, lo_base+15]
            int hi_end  = i + (l_hi - 16) * 16;     // me in (hi_end-16, hi_end]

            // Phase B: low lanes resolve ms, high lanes resolve me. One probe each.
            int q;
            bool eq2;
            if (lane < 16) {
                q = lo_base + lane;                 // q <= i, may be < 0
                eq2 = (q >= 0) && (__ldg(batch + q) == bi);
            } else {
                q = hi_end - 31 + lane;             // q in [hi_end-15, hi_end]
                eq2 = (q < n) && (__ldg(batch + q) == bi);
            }
            unsigned m2 = __ballot_sync(0xffffffffu, eq2);
            unsigned lom = m2 & 0xFFFFu;            // nonzero
            unsigned him = m2 >> 16;                // may be zero
            ms = lo_base + (__ffs(lom) - 1);        // first eq index
            me = hi_end - 15 + (32 - __clz(him));   // one past last eq index
        }
    }

    // ---- selection ----
    u64 held;
    int c0;
    if (ms < 32) {
        u64 seed = chunk_key(0, lane, n, i, ms, me, xi, yi, zi, sqni, pos);
        held = bitonic_sort32<true>(seed, lane);
        c0 = 1;
    } else {
        held = ((u64)__float_as_uint(CUTOFF_SQ) << 32) | (unsigned)lane;
        c0 = ms >> 5;
    }
    int cend = (me - 1) >> 5;

    if (c0 <= cend) {
        // software-pipelined: issue next chunk's loads before sorting current
        u64 cand = chunk_key(c0, lane, n, i, ms, me, xi, yi, zi, sqni, pos);
        for (int c = c0;;) {
            int cn = c + 1;
            bool more = (cn <= cend);
            u64 next = 0;
            if (more) next = chunk_key(cn, lane, n, i, ms, me, xi, yi, zi, sqni, pos);
            cand = bitonic_sort32<false>(cand, lane);   // desc: no reverse in merge
            held = merge_keep32(held, cand, lane);
            if (!more) break;
            cand = next;
            c = cn;
        }
    }

    // Output: [edge_index[0] (N*K), edge_index[1] (N*K), edge_weight (N*K)]
    unsigned int nb = (unsigned int)(held & 0xffffffffu);
    float sqv = __uint_as_float((unsigned int)(held >> 32));
    float wgt = sqrtf(sqv);                // sqrt(100)=10 exactly for fills/masked
    int NK = n * KNN_K;
    int base = i * KNN_K + lane;
    out[base]          = (float)nb;        // neighbor index
    out[NK + base]     = (float)i;         // source row
    out[2 * NK + base] = wgt;              // distance weight
}

extern "C" void kernel_launch(void* const* d_in, const int* in_sizes, int n_in,
                              void* d_out, int out_size)
{
    const float* pos   = (const float*)d_in[0];
    const int*   batch = (const int*)d_in[1];
    float*       out   = (float*)d_out;
    int n = in_sizes[1];  // batch has N elements

    int threads = 256;                       // 8 warps/block, 1 warp per row
    int blocks  = (n * 32 + threads - 1) / threads;
    knn_kernel<<<blocks, threads>>>(pos, batch, out, n);
}

// round 14
// speedup vs baseline: 1.2917x; 1.1348x over previous
#include <cuda_runtime.h>

#define KNN_K 32
#define CUTOFF_SQ 100.0f
#define CUTOFF_SQ_BITS 0x42C80000u   // __float_as_uint(100.0f)

typedef unsigned long long u64;
#define SENTINEL 0xFFFFFFFFFFFFFFFFull

// Conditional-take compare-exchange. Equal keys are identical entries
// (key embeds the index), so either choice is correct on ties.
__device__ __forceinline__ void ce_swap(u64& key, u64 other, bool keep_min) {
    bool take = (other < key) == keep_min;
    if (take) key = other;
}

// res sorted asc (32 best so far), cand sorted DESC: elementwise min is a
// bitonic sequence holding exactly the 32 smallest of the 64; 5-stage
// cleanup re-sorts asc.
__device__ __forceinline__ u64 merge_keep32(u64 res, u64 cand_desc, int lane) {
    u64 lo = (res < cand_desc) ? res : cand_desc;
    #pragma unroll
    for (int j = 16; j >= 1; j >>= 1) {
        u64 o = __shfl_xor_sync(0xffffffffu, lo, j);
        ce_swap(lo, o, (lane & j) == 0);
    }
    return lo;
}

// Key for gathered candidate j = ms + 32t + lane (so j >= ms always):
// (float_bits(masked_sq) << 32) | j. sq >= 0 so float bits are u32-monotone;
// u64 compare == (sq asc, idx asc) == reference (d asc, idx asc) since sqrt
// is monotone and sqrt_rn(100) = 10 exactly. Slots with j >= me get SENTINEL;
// they can never reach the final top-32 because the 32 seed fills (value
// 100.0) all rank strictly below any sentinel.
__device__ __forceinline__ u64 gkey(int j, int i, int me,
                                    float xi, float yi, float zi, float sqni,
                                    const float* __restrict__ pos)
{
    if (j >= me) return SENTINEL;
    float xj = __ldg(pos + 3 * j);
    float yj = __ldg(pos + 3 * j + 1);
    float zj = __ldg(pos + 3 * j + 2);
    // Reference's gram-matrix expansion (numerical parity):
    float sqnj = xj * xj + yj * yj + zj * zj;
    float dt   = xi * xj + yi * yj + zi * zj;
    float sq   = sqni + sqnj - 2.0f * dt;
    sq = fmaxf(sq, 0.0f);
    bool masked = (j == i) | (sq > CUTOFF_SQ);
    float v = masked ? CUTOFF_SQ : sq;
    return ((u64)__float_as_uint(v) << 32) | (unsigned)j;
}

// Fallback: warp binary search (even lanes lower_bound, odd lanes upper_bound).
__device__ __forceinline__ void mol_bounds_bsearch(
    const int* __restrict__ batch, int n, int bi, int lane, int& ms, int& me)
{
    int lo = 0, hi = n;
    bool upper = (lane & 1);
    while (lo < hi) {
        int mid = (lo + hi) >> 1;
        int v = __ldg(batch + mid);
        bool go = upper ? (v <= bi) : (v < bi);
        if (go) lo = mid + 1; else hi = mid;
    }
    ms = __shfl_sync(0xffffffffu, lo, 0);
    me = __shfl_sync(0xffffffffu, lo, 1);
}

// One warp per row i.
// Exactness: the row's true top-32 is drawn from
//   {in-molecule candidates j in [ms, me)} ∪ {fills (100.0, j), j outside}.
// The 32 smallest fills are exactly s_l = (l < ms) ? l : me + (l - ms): every
// other fill has 32 entries ranking at-or-below it, so it can never appear.
// We take top-32 of all candidate groups, then merge with those 32 seeds —
// exact for any ms/me, no special cases.
__global__ void __launch_bounds__(256)
knn_kernel(const float* __restrict__ pos, const int* __restrict__ batch,
           float* __restrict__ out, int n)
{
    int w    = (blockIdx.x * blockDim.x + threadIdx.x) >> 5;
    int lane = threadIdx.x & 31;
    if (w >= n) return;

    // Stratified row mapping (verified kernel-time win in R11): block b's 8
    // warps take rows b, b+n/8, ..., b+7n/8 — per-block work becomes an
    // 8-stratum sample of molecule sizes, equalizing per-SM instruction mass
    // across the single resident wave. Bijective when 8 | n.
    int i;
    if ((n & 7) == 0) {
        i = (w & 7) * (n >> 3) + (w >> 3);
    } else {
        i = w;
    }

    float xi = __ldg(pos + 3 * i);
    float yi = __ldg(pos + 3 * i + 1);
    float zi = __ldg(pos + 3 * i + 2);
    int   bi = __ldg(batch + i);
    float sqni = xi * xi + yi * yi + zi * zi;

    // ---- molecule bounds: 2-probe warp-cooperative search around i ----
    int ms, me;
    {
        // Phase A: stride-16 probes covering [i-256, i+240].
        int p = i + (lane - 16) * 16;
        bool inb = (p >= 0) && (p < n);
        bool eq  = inb && (__ldg(batch + p) == bi);
        unsigned m = __ballot_sync(0xffffffffu, eq);
        unsigned low_ne = (~m) & 0xFFFFu;
        unsigned hi_ne  = (~m) >> 16;

        if (low_ne == 0u || hi_ne == 0u) {
            mol_bounds_bsearch(batch, n, bi, lane, ms, me);  // exact fallback
        } else {
            int l_lo = 31 - __clz(low_ne);
            int l_hi = 16 + (__ffs(hi_ne) - 1);
            int lo_base = i + (l_lo - 16) * 16 + 1;
            int hi_end  = i + (l_hi - 16) * 16;
            int q;
            bool eq2;
            if (lane < 16) {
                q = lo_base + lane;
                eq2 = (q >= 0) && (__ldg(batch + q) == bi);
            } else {
                q = hi_end - 31 + lane;
                eq2 = (q < n) && (__ldg(batch + q) == bi);
            }
            unsigned m2 = __ballot_sync(0xffffffffu, eq2);
            unsigned lom = m2 & 0xFFFFu;
            unsigned him = m2 >> 16;
            ms = lo_base + (__ffs(lom) - 1);
            me = hi_end - 15 + (32 - __clz(him));
        }
    }

    // ---- selection over gathered groups j = ms + 32t + lane ----
    int span = me - ms;                 // >= 1 (molecule contains i)
    int T = (span + 31) >> 5;           // number of 32-wide groups
    u64 res;                            // running top-32, sorted asc
    int t;

    if (T >= 2) {
        // First pair: sort A asc and B desc in one interleaved unrolled loop
        // (independent CE chains -> 2-wide ILP on the shuffle latency).
        u64 A = gkey(ms + lane,      i, me, xi, yi, zi, sqni, pos);
        u64 B = gkey(ms + 32 + lane, i, me, xi, yi, zi, sqni, pos);
        #pragma unroll
        for (int k = 2; k <= 32; k <<= 1) {
            #pragma unroll
            for (int j = k >> 1; j >= 1; j >>= 1) {
                u64 oA = __shfl_xor_sync(0xffffffffu, A, j);
                u64 oB = __shfl_xor_sync(0xffffffffu, B, j);
                bool km = (((lane & k) == 0) == ((lane & j) == 0));
                ce_swap(A, oA, km);     // ascending
                ce_swap(B, oB, !km);    // descending
            }
        }
        // top-32 of A∪B: min(asc, desc) is bitonic; 5-stage asc cleanup.
        res = merge_keep32(A, B, lane);
        t = 2;
    } else {
        // Single group: plain ascending sort.
        u64 A = gkey(ms + lane, i, me, xi, yi, zi, sqni, pos);
        #pragma unroll
        for (int k = 2; k <= 32; k <<= 1) {
            #pragma unroll
            for (int j = k >> 1; j >= 1; j >>= 1) {
                u64 oA = __shfl_xor_sync(0xffffffffu, A, j);
                bool km = (((lane & k) == 0) == ((lane & j) == 0));
                ce_swap(A, oA, km);
            }
        }
        res = A;
        t = 1;
    }

    // Remaining groups: software-pipelined — issue the next group's loads
    // before the current group's 15-stage sort so gather latency is hidden.
    if (t < T) {
        u64 C = gkey(ms + t * 32 + lane, i, me, xi, yi, zi, sqni, pos);
        for (;;) {
            int tn = t + 1;
            bool more = (tn < T);
            u64 next = 0;
            if (more) next = gkey(ms + tn * 32 + lane, i, me, xi, yi, zi, sqni, pos);
            #pragma unroll
            for (int k = 2; k <= 32; k <<= 1) {
                #pragma unroll
                for (int j = k >> 1; j >= 1; j >>= 1) {
                    u64 oC = __shfl_xor_sync(0xffffffffu, C, j);
                    bool km = (((lane & k) == 0) == ((lane & j) == 0));
                    ce_swap(C, oC, !km);    // descending
                }
            }
            res = merge_keep32(res, C, lane);
            if (!more) break;
            C = next;
            t = tn;
        }
    }

    // ---- final merge with the 32 seed fills, generated DESC arithmetically
    // (equal values 100.0, so descending == descending index; no sort needed).
    {
        int l2 = 31 - lane;
        int sidx = (l2 < ms) ? l2 : me + (l2 - ms);
        u64 seed_desc = (sidx < n)
            ? (((u64)CUTOFF_SQ_BITS << 32) | (unsigned)sidx)
            : SENTINEL;
        res = merge_keep32(res, seed_desc, lane);
    }

    // Output: [edge_index[0] (N*K), edge_index[1] (N*K), edge_weight (N*K)]
    unsigned int nb = (unsigned int)(res & 0xffffffffu);
    float sqv = __uint_as_float((unsigned int)(res >> 32));
    float wgt = sqrtf(sqv);             // sqrt(100)=10 exactly for fills/masked
    int NK = n * KNN_K;
    int base = i * KNN_K + lane;
    out[base]          = (float)nb;     // neighbor index
    out[NK + base]     = (float)i;      // source row
    out[2 * NK + base] = wgt;           // distance weight
}

extern "C" void kernel_launch(void* const* d_in, const int* in_sizes, int n_in,
                              void* d_out, int out_size)
{
    const float* pos   = (const float*)d_in[0];
    const int*   batch = (const int*)d_in[1];
    float*       out   = (float*)d_out;
    int n = in_sizes[1];  // batch has N elements

    int threads = 256;                       // 8 warps/block, 1 warp per row
    int blocks  = (n * 32 + threads - 1) / threads;
    knn_kernel<<<blocks, threads>>>(pos, batch, out, n);
}

// round 15
// speedup vs baseline: 1.5685x; 1.2143x over previous
#include <cuda_runtime.h>

#define KNN_K 32
#define CUTOFF_SQ 100.0f
#define CUTOFF_SQ_BITS 0x42C80000u   // __float_as_uint(100.0f)

typedef unsigned long long u64;
#define SENTINEL 0xFFFFFFFFFFFFFFFFull

// Conditional-take compare-exchange. Equal keys are identical entries
// (key embeds the index), so either choice is correct on ties.
__device__ __forceinline__ void ce_swap(u64& key, u64 other, bool keep_min) {
    bool take = (other < key) == keep_min;
    if (take) key = other;
}

// res sorted asc (32 best so far), cand sorted DESC: elementwise min is a
// bitonic sequence holding exactly the 32 smallest of the 64; 5-stage
// cleanup re-sorts asc.
__device__ __forceinline__ u64 merge_keep32(u64 res, u64 cand_desc, int lane) {
    u64 lo = (res < cand_desc) ? res : cand_desc;
    #pragma unroll
    for (int j = 16; j >= 1; j >>= 1) {
        u64 o = __shfl_xor_sync(0xffffffffu, lo, j);
        ce_swap(lo, o, (lane & j) == 0);
    }
    return lo;
}

// Key for gathered candidate j = ms + 32t + lane (so j >= ms always):
// (float_bits(masked_sq) << 32) | j. sq >= 0 so float bits are u32-monotone;
// u64 compare == (sq asc, idx asc) == reference (d asc, idx asc) since sqrt
// is monotone and sqrt_rn(100) = 10 exactly. Slots with j >= me get SENTINEL;
// they can never reach the final top-32 because the 32 seed fills (value
// 100.0) all rank strictly below any sentinel.
__device__ __forceinline__ u64 gkey(int j, int i, int me,
                                    float xi, float yi, float zi, float sqni,
                                    const float* __restrict__ pos)
{
    if (j >= me) return SENTINEL;
    float xj = __ldg(pos + 3 * j);
    float yj = __ldg(pos + 3 * j + 1);
    float zj = __ldg(pos + 3 * j + 2);
    // Reference's gram-matrix expansion (numerical parity):
    float sqnj = xj * xj + yj * yj + zj * zj;
    float dt   = xi * xj + yi * yj + zi * zj;
    float sq   = sqni + sqnj - 2.0f * dt;
    sq = fmaxf(sq, 0.0f);
    bool masked = (j == i) | (sq > CUTOFF_SQ);
    float v = masked ? CUTOFF_SQ : sq;
    return ((u64)__float_as_uint(v) << 32) | (unsigned)j;
}

// Fallback: warp binary search (even lanes lower_bound, odd lanes upper_bound).
__device__ __forceinline__ void mol_bounds_bsearch(
    const int* __restrict__ batch, int n, int bi, int lane, int& ms, int& me)
{
    int lo = 0, hi = n;
    bool upper = (lane & 1);
    while (lo < hi) {
        int mid = (lo + hi) >> 1;
        int v = __ldg(batch + mid);
        bool go = upper ? (v <= bi) : (v < bi);
        if (go) lo = mid + 1; else hi = mid;
    }
    ms = __shfl_sync(0xffffffffu, lo, 0);
    me = __shfl_sync(0xffffffffu, lo, 1);
}

// One warp per row i.
// Exactness: the row's true top-32 is drawn from
//   {in-molecule candidates j in [ms, me)} ∪ {fills (100.0, j), j outside}.
// The 32 smallest fills are exactly s_l = (l < ms) ? l : me + (l - ms): every
// other fill has 32 entries ranking at-or-below it, so it can never appear.
// We take top-32 of all candidate groups, then merge with those 32 seeds —
// exact for any ms/me, no special cases.
__global__ void __launch_bounds__(256, 7)
knn_kernel(const float* __restrict__ pos, const int* __restrict__ batch,
           float* __restrict__ out, int n)
{
    int w    = (blockIdx.x * blockDim.x + threadIdx.x) >> 5;
    int lane = threadIdx.x & 31;
    if (w >= n) return;

    // Stratified row mapping (verified win): block b's 8 warps take rows
    // b, b+n/8, ..., b+7n/8 — per-block work becomes an 8-stratum sample of
    // molecule sizes, equalizing per-SM instruction mass. Bijective when 8|n.
    int i;
    if ((n & 7) == 0) {
        i = (w & 7) * (n >> 3) + (w >> 3);
    } else {
        i = w;
    }

    float xi = __ldg(pos + 3 * i);
    float yi = __ldg(pos + 3 * i + 1);
    float zi = __ldg(pos + 3 * i + 2);
    int   bi = __ldg(batch + i);
    float sqni = xi * xi + yi * yi + zi * zi;

    // ---- molecule bounds: 2-probe warp-cooperative search around i ----
    int ms, me;
    {
        // Phase A: stride-16 probes covering [i-256, i+240].
        int p = i + (lane - 16) * 16;
        bool inb = (p >= 0) && (p < n);
        bool eq  = inb && (__ldg(batch + p) == bi);
        unsigned m = __ballot_sync(0xffffffffu, eq);
        unsigned low_ne = (~m) & 0xFFFFu;
        unsigned hi_ne  = (~m) >> 16;

        if (low_ne == 0u || hi_ne == 0u) {
            mol_bounds_bsearch(batch, n, bi, lane, ms, me);  // exact fallback
        } else {
            int l_lo = 31 - __clz(low_ne);
            int l_hi = 16 + (__ffs(hi_ne) - 1);
            int lo_base = i + (l_lo - 16) * 16 + 1;
            int hi_end  = i + (l_hi - 16) * 16;
            int q;
            bool eq2;
            if (lane < 16) {
                q = lo_base + lane;
                eq2 = (q >= 0) && (__ldg(batch + q) == bi);
            } else {
                q = hi_end - 31 + lane;
                eq2 = (q < n) && (__ldg(batch + q) == bi);
            }
            unsigned m2 = __ballot_sync(0xffffffffu, eq2);
            unsigned lom = m2 & 0xFFFFu;
            unsigned him = m2 >> 16;
            ms = lo_base + (__ffs(lom) - 1);
            me = hi_end - 15 + (32 - __clz(him));
        }
    }

    // ---- selection over gathered groups j = ms + 32t + lane ----
    int span = me - ms;                 // >= 1 (molecule contains i)
    int T = (span + 31) >> 5;           // number of 32-wide groups
    u64 res;                            // running top-32, sorted asc

    if (T == 3) {
        // Dominant expensive case (~half the rows): sort A asc, B desc, C asc
        // in ONE interleaved 15-stage loop (3-wide ILP), then half-cleaner
        // chain: min(A,B) bitonic -> cleanup desc -> min(C, .) bitonic ->
        // cleanup asc. 31 stages total vs 48 for the sequential path.
        u64 A = gkey(ms + lane,      i, me, xi, yi, zi, sqni, pos);
        u64 B = gkey(ms + 32 + lane, i, me, xi, yi, zi, sqni, pos);
        u64 C = gkey(ms + 64 + lane, i, me, xi, yi, zi, sqni, pos);
        #pragma unroll
        for (int k = 2; k <= 32; k <<= 1) {
            #pragma unroll
            for (int j = k >> 1; j >= 1; j >>= 1) {
                u64 oA = __shfl_xor_sync(0xffffffffu, A, j);
                u64 oB = __shfl_xor_sync(0xffffffffu, B, j);
                u64 oC = __shfl_xor_sync(0xffffffffu, C, j);
                bool km = (((lane & k) == 0) == ((lane & j) == 0));
                ce_swap(A, oA, km);     // ascending
                ce_swap(B, oB, !km);    // descending
                ce_swap(C, oC, km);     // ascending
            }
        }
        // m = 32 smallest of A∪B, bitonic; clean to DESC.
        u64 m = (A < B) ? A : B;
        #pragma unroll
        for (int j = 16; j >= 1; j >>= 1) {
            u64 o = __shfl_xor_sync(0xffffffffu, m, j);
            ce_swap(m, o, (lane & j) != 0);
        }
        // m2 = 32 smallest of C∪m = 32 smallest of all three; clean to ASC.
        u64 m2 = (C < m) ? C : m;
        #pragma unroll
        for (int j = 16; j >= 1; j >>= 1) {
            u64 o = __shfl_xor_sync(0xffffffffu, m2, j);
            ce_swap(m2, o, (lane & j) == 0);
        }
        res = m2;
    } else if (T == 2) {
        // Pair: sort A asc & B desc interleaved, then min + asc cleanup.
        u64 A = gkey(ms + lane,      i, me, xi, yi, zi, sqni, pos);
        u64 B = gkey(ms + 32 + lane, i, me, xi, yi, zi, sqni, pos);
        #pragma unroll
        for (int k = 2; k <= 32; k <<= 1) {
            #pragma unroll
            for (int j = k >> 1; j >= 1; j >>= 1) {
                u64 oA = __shfl_xor_sync(0xffffffffu, A, j);
                u64 oB = __shfl_xor_sync(0xffffffffu, B, j);
                bool km = (((lane & k) == 0) == ((lane & j) == 0));
                ce_swap(A, oA, km);     // ascending
                ce_swap(B, oB, !km);    // descending
            }
        }
        res = merge_keep32(A, B, lane);
    } else if (T == 1) {
        u64 A = gkey(ms + lane, i, me, xi, yi, zi, sqni, pos);
        #pragma unroll
        for (int k = 2; k <= 32; k <<= 1) {
            #pragma unroll
            for (int j = k >> 1; j >= 1; j >>= 1) {
                u64 oA = __shfl_xor_sync(0xffffffffu, A, j);
                bool km = (((lane & k) == 0) == ((lane & j) == 0));
                ce_swap(A, oA, km);
            }
        }
        res = A;
    } else {
        // Rare T >= 4: interleaved first pair, then pipelined desc+merge loop.
        u64 A = gkey(ms + lane,      i, me, xi, yi, zi, sqni, pos);
        u64 B = gkey(ms + 32 + lane, i, me, xi, yi, zi, sqni, pos);
        #pragma unroll
        for (int k = 2; k <= 32; k <<= 1) {
            #pragma unroll
            for (int j = k >> 1; j >= 1; j >>= 1) {
                u64 oA = __shfl_xor_sync(0xffffffffu, A, j);
                u64 oB = __shfl_xor_sync(0xffffffffu, B, j);
                bool km = (((lane & k) == 0) == ((lane & j) == 0));
                ce_swap(A, oA, km);
                ce_swap(B, oB, !km);
            }
        }
        res = merge_keep32(A, B, lane);
        int t = 2;
        u64 C = gkey(ms + t * 32 + lane, i, me, xi, yi, zi, sqni, pos);
        for (;;) {
            int tn = t + 1;
            bool more = (tn < T);
            u64 next = 0;
            if (more) next = gkey(ms + tn * 32 + lane, i, me, xi, yi, zi, sqni, pos);
            #pragma unroll
            for (int k = 2; k <= 32; k <<= 1) {
                #pragma unroll
                for (int j = k >> 1; j >= 1; j >>= 1) {
                    u64 oC = __shfl_xor_sync(0xffffffffu, C, j);
                    bool km = (((lane & k) == 0) == ((lane & j) == 0));
                    ce_swap(C, oC, !km);    // descending
                }
            }
            res = merge_keep32(res, C, lane);
            if (!more) break;
            C = next;
            t = tn;
        }
    }

    // ---- final merge with the 32 seed fills, generated DESC arithmetically
    // (equal values 100.0, so descending == descending index; no sort needed).
    {
        int l2 = 31 - lane;
        int sidx = (l2 < ms) ? l2 : me + (l2 - ms);
        u64 seed_desc = (sidx < n)
            ? (((u64)CUTOFF_SQ_BITS << 32) | (unsigned)sidx)
            : SENTINEL;
        res = merge_keep32(res, seed_desc, lane);
    }

    // Output: [edge_index[0] (N*K), edge_index[1] (N*K), edge_weight (N*K)]
    unsigned int nb = (unsigned int)(res & 0xffffffffu);
    float sqv = __uint_as_float((unsigned int)(res >> 32));
    float wgt = sqrtf(sqv);             // sqrt(100)=10 exactly for fills/masked
    int NK = n * KNN_K;
    int base = i * KNN_K + lane;
    out[base]          = (float)nb;     // neighbor index
    out[NK + base]     = (float)i;      // source row
    out[2 * NK + base] = wgt;           // distance weight
}

extern "C" void kernel_launch(void* const* d_in, const int* in_sizes, int n_in,
                              void* d_out, int out_size)
{
    const float* pos   = (const float*)d_in[0];
    const int*   batch = (const int*)d_in[1];
    float*       out   = (float*)d_out;
    int n = in_sizes[1];  // batch has N elements

    int threads = 256;                       // 8 warps/block, 1 warp per row
    int blocks  = (n * 32 + threads - 1) / threads;
    knn_kernel<<<blocks, threads>>>(pos, batch, out, n);
}